// round 7
// baseline (speedup 1.0000x reference)
#include <cuda_runtime.h>
#include <cuda_bf16.h>
#include <cstdint>
#include <math.h>

#define L_LAYERS 4
#define BATCH    8
#define PHN      24
#define PWN      24
#define PATCHES  576
#define DIM      1024
#define NRL      12
#define NPAIRS   28
#define OUTH     336
#define OUTW     336
#define PADP     640            // storage stride (rows 576+ unused)
#define TILEM    192
#define KS       32             // k per slab
#define NSLAB    32             // 1024/32
#define STAGES   4
#define ROWB     80             // smem row stride bytes (64 data + 16 pad)
#define STAGEB   (2 * TILEM * ROWB)  // A+B per stage = 30720
#define SMEM_DYN (STAGES * STAGEB)   // 122880
#define NTHR     384            // 12 warps, warp grid 3x4, warp tile 64x48

// ---------------- device scratch ----------------
__device__ __align__(16) __nv_bfloat16 g_featn[(size_t)NRL * BATCH * PADP * DIM];
__device__ unsigned g_keys[NRL * BATCH * PADP * BATCH];
__device__ float    g_scores[BATCH * PATCHES];

__device__ __forceinline__ unsigned enc_f(float x) {
    unsigned u = __float_as_uint(x);
    return (u & 0x80000000u) ? ~u : (u | 0x80000000u);
}
__device__ __forceinline__ float dec_f(unsigned k) {
    unsigned u = (k & 0x80000000u) ? (k & 0x7FFFFFFFu) : ~k;
    return __uint_as_float(u);
}

__device__ __forceinline__ uint32_t smem_u32(const void* p) {
    uint32_t a;
    asm("{ .reg .u64 t; cvta.to.shared.u64 t, %1; cvt.u32.u64 %0, t; }" : "=r"(a) : "l"(p));
    return a;
}

#define CP16(dst, src) asm volatile("cp.async.cg.shared.global [%0], [%1], 16;" :: "r"(dst), "l"(src) : "memory")
#define CP_COMMIT()    asm volatile("cp.async.commit_group;" ::: "memory")

#define LDSM_X4(r0, r1, r2, r3, a) \
    asm volatile("ldmatrix.sync.aligned.m8n8.x4.shared.b16 {%0,%1,%2,%3}, [%4];" \
        : "=r"(r0), "=r"(r1), "=r"(r2), "=r"(r3) : "r"(a))

#define MMA16816(c, a, b) \
    asm volatile("mma.sync.aligned.m16n8k16.row.col.f32.bf16.bf16.f32 " \
        "{%0,%1,%2,%3}, {%4,%5,%6,%7}, {%8,%9}, {%0,%1,%2,%3};" \
        : "+f"((c)[0]), "+f"((c)[1]), "+f"((c)[2]), "+f"((c)[3]) \
        : "r"((a)[0]), "r"((a)[1]), "r"((a)[2]), "r"((a)[3]), "r"((b)[0]), "r"((b)[1]))

// ---------------- init ----------------
__global__ void init_keys_kernel() {
    int i = blockIdx.x * 256 + threadIdx.x;
    if (i < NRL * BATCH * PADP * BATCH) g_keys[i] = 0u;
}

// ---------------- pool (all 3 radii, one 5x5 read) + normalize -> bf16 ------
__global__ void pool_norm_kernel(const float* __restrict__ feat) {
    int p = blockIdx.x, b = blockIdx.y, l = blockIdx.z;
    int ph = p / PWN, pw = p % PWN;
    int t = threadIdx.x;
    int d0 = t * 4;

    const float* base = feat + ((size_t)(l * BATCH + b) * PATCHES) * DIM;

    float4 s5 = make_float4(0.f, 0.f, 0.f, 0.f);
    float4 s3 = make_float4(0.f, 0.f, 0.f, 0.f);
    float4 s1 = make_float4(0.f, 0.f, 0.f, 0.f);

    #pragma unroll
    for (int dy = -2; dy <= 2; ++dy) {
        int y = ph + dy;
        if ((unsigned)y >= (unsigned)PHN) continue;
        #pragma unroll
        for (int dx = -2; dx <= 2; ++dx) {
            int x = pw + dx;
            if ((unsigned)x >= (unsigned)PWN) continue;
            const float4 v = *(const float4*)(base + (size_t)(y * PWN + x) * DIM + d0);
            s5.x += v.x; s5.y += v.y; s5.z += v.z; s5.w += v.w;
            if (dy >= -1 && dy <= 1 && dx >= -1 && dx <= 1) {
                s3.x += v.x; s3.y += v.y; s3.z += v.z; s3.w += v.w;
                if (dy == 0 && dx == 0) s1 = v;
            }
        }
    }
    s3.x *= (1.f/9.f);  s3.y *= (1.f/9.f);  s3.z *= (1.f/9.f);  s3.w *= (1.f/9.f);
    s5.x *= (1.f/25.f); s5.y *= (1.f/25.f); s5.z *= (1.f/25.f); s5.w *= (1.f/25.f);

    float q1 = s1.x*s1.x + s1.y*s1.y + s1.z*s1.z + s1.w*s1.w;
    float q3 = s3.x*s3.x + s3.y*s3.y + s3.z*s3.z + s3.w*s3.w;
    float q5 = s5.x*s5.x + s5.y*s5.y + s5.z*s5.z + s5.w*s5.w;
    #pragma unroll
    for (int o = 16; o > 0; o >>= 1) {
        q1 += __shfl_xor_sync(0xffffffffu, q1, o);
        q3 += __shfl_xor_sync(0xffffffffu, q3, o);
        q5 += __shfl_xor_sync(0xffffffffu, q5, o);
    }
    __shared__ float ws[3][8];
    __shared__ float rn[3];
    if ((t & 31) == 0) { ws[0][t >> 5] = q1; ws[1][t >> 5] = q3; ws[2][t >> 5] = q5; }
    __syncthreads();
    if (t < 3) {
        float x = 0.f;
        #pragma unroll
        for (int w = 0; w < 8; ++w) x += ws[t][w];
        rn[t] = rsqrtf(x);
    }
    __syncthreads();

    float4 vv[3] = { s1, s3, s5 };
    #pragma unroll
    for (int ri = 0; ri < 3; ++ri) {
        float r = rn[ri];
        __nv_bfloat162 lo = __floats2bfloat162_rn(vv[ri].x * r, vv[ri].y * r);
        __nv_bfloat162 hi = __floats2bfloat162_rn(vv[ri].z * r, vv[ri].w * r);
        uint2 pk = make_uint2(*(unsigned*)&lo, *(unsigned*)&hi);
        int z = ri * 4 + l;
        *(uint2*)(g_featn + ((size_t)(z * BATCH + b) * PADP + p) * DIM + d0) = pk;
    }
}

// ---------------- bf16 mma.sync fused GEMM + bidirectional max ----------------
// CTA tile 192x192, 12 warps (3x4) of 64x48, K slabs of 32, 4-stage cp.async.
__device__ __forceinline__ void load_slab(uint32_t sA, const char* gA, const char* gB, int t) {
    int r0 = t >> 2, c = t & 3;          // r0: 0..95
    #pragma unroll
    for (int h = 0; h < 2; ++h) {
        int r = r0 + h * 96;
        CP16(sA + r * ROWB + c * 16, gA + (size_t)r * (DIM * 2) + c * 16);
    }
    #pragma unroll
    for (int h = 0; h < 2; ++h) {
        int r = r0 + h * 96;
        CP16(sA + (TILEM + r) * ROWB + c * 16, gB + (size_t)r * (DIM * 2) + c * 16);
    }
}

__global__ void __launch_bounds__(NTHR, 1) gemm_max_mma() {
    extern __shared__ __align__(16) char dsm[];
    uint32_t sbase = smem_u32(dsm);

    int t = threadIdx.x;
    int wid = t >> 5, lane = t & 31;
    int warp_m = wid >> 2;              // 0..2 : row groups of 64
    int warp_n = wid & 3;               // 0..3 : col groups of 48

    int tile = blockIdx.x;
    int ti = tile / 3, tj = tile % 3;
    int pair = blockIdx.y, rl = blockIdx.z;

    int b = 0, rem = pair;
    #pragma unroll
    for (int bb = 0; bb < 7; ++bb) {
        int cnt = 7 - bb;
        if (rem < cnt) { b = bb; break; }
        rem -= cnt;
    }
    int c = b + 1 + rem;

    const char* gA = (const char*)(g_featn + ((size_t)(rl * BATCH + b) * PADP + ti * TILEM) * DIM);
    const char* gB = (const char*)(g_featn + ((size_t)(rl * BATCH + c) * PADP + tj * TILEM) * DIM);

    float acc[4][6][4];
    #pragma unroll
    for (int mi = 0; mi < 4; ++mi)
        #pragma unroll
        for (int ni = 0; ni < 6; ++ni)
            #pragma unroll
            for (int j = 0; j < 4; ++j) acc[mi][ni][j] = 0.f;

    uint32_t aoff = (uint32_t)((warp_m * 64 + (lane & 15)) * ROWB + (lane >> 4) * 16);
    uint32_t boff = (uint32_t)((TILEM + warp_n * 48 + (lane >> 4) * 8 + (lane & 7)) * ROWB + ((lane >> 3) & 1) * 16);

    #pragma unroll
    for (int s = 0; s < 3; ++s) {
        load_slab(sbase + s * STAGEB, gA + (size_t)s * (KS * 2), gB + (size_t)s * (KS * 2), t);
        CP_COMMIT();
    }

    for (int kc = 0; kc < NSLAB; ++kc) {
        if (kc < NSLAB - 2)       asm volatile("cp.async.wait_group 2;" ::: "memory");
        else if (kc == NSLAB - 2) asm volatile("cp.async.wait_group 1;" ::: "memory");
        else                      asm volatile("cp.async.wait_group 0;" ::: "memory");
        __syncthreads();

        if (kc + 3 < NSLAB) {
            int bufw = (kc + 3) & 3;
            load_slab(sbase + bufw * STAGEB,
                      gA + (size_t)(kc + 3) * (KS * 2), gB + (size_t)(kc + 3) * (KS * 2), t);
            CP_COMMIT();
        }

        uint32_t Sb = sbase + (kc & 3) * STAGEB;

        #pragma unroll
        for (int ks = 0; ks < 2; ++ks) {
            uint32_t afr[4][4];
            #pragma unroll
            for (int mi = 0; mi < 4; ++mi)
                LDSM_X4(afr[mi][0], afr[mi][1], afr[mi][2], afr[mi][3],
                        Sb + aoff + mi * 16 * ROWB + ks * 32);
            uint32_t bfr[6][2];
            #pragma unroll
            for (int np = 0; np < 3; ++np)
                LDSM_X4(bfr[np * 2][0], bfr[np * 2][1], bfr[np * 2 + 1][0], bfr[np * 2 + 1][1],
                        Sb + boff + np * 16 * ROWB + ks * 32);
            #pragma unroll
            for (int mi = 0; mi < 4; ++mi)
                #pragma unroll
                for (int ni = 0; ni < 6; ++ni)
                    MMA16816(acc[mi][ni], afr[mi], bfr[ni]);
        }
    }

    // ---------------- epilogue: bidirectional max ----------------
    // last loop read stage 3; stage-0 smem region is free for reductions.
    float* rowsmem = (float*)dsm;            // [4][192] by warp_n
    float* colsmem = rowsmem + 4 * 192;      // [3][192] by warp_m

    #pragma unroll
    for (int mi = 0; mi < 4; ++mi) {
        float rm0 = -1e30f, rm1 = -1e30f;
        #pragma unroll
        for (int ni = 0; ni < 6; ++ni) {
            rm0 = fmaxf(rm0, fmaxf(acc[mi][ni][0], acc[mi][ni][1]));
            rm1 = fmaxf(rm1, fmaxf(acc[mi][ni][2], acc[mi][ni][3]));
        }
        #pragma unroll
        for (int o = 1; o < 4; o <<= 1) {
            rm0 = fmaxf(rm0, __shfl_xor_sync(0xffffffffu, rm0, o));
            rm1 = fmaxf(rm1, __shfl_xor_sync(0xffffffffu, rm1, o));
        }
        if ((lane & 3) == 0) {
            int lr = warp_m * 64 + mi * 16 + (lane >> 2);
            rowsmem[warp_n * 192 + lr]     = rm0;
            rowsmem[warp_n * 192 + lr + 8] = rm1;
        }
    }

    #pragma unroll
    for (int ni = 0; ni < 6; ++ni) {
        float cm0 = -1e30f, cm1 = -1e30f;
        #pragma unroll
        for (int mi = 0; mi < 4; ++mi) {
            cm0 = fmaxf(cm0, fmaxf(acc[mi][ni][0], acc[mi][ni][2]));
            cm1 = fmaxf(cm1, fmaxf(acc[mi][ni][1], acc[mi][ni][3]));
        }
        #pragma unroll
        for (int o = 4; o < 32; o <<= 1) {
            cm0 = fmaxf(cm0, __shfl_xor_sync(0xffffffffu, cm0, o));
            cm1 = fmaxf(cm1, __shfl_xor_sync(0xffffffffu, cm1, o));
        }
        if (lane < 4) {
            int lc = warp_n * 48 + ni * 8 + lane * 2;
            colsmem[warp_m * 192 + lc]     = cm0;
            colsmem[warp_m * 192 + lc + 1] = cm1;
        }
    }
    __syncthreads();

    if (t < 192) {
        float mr = fmaxf(fmaxf(rowsmem[t], rowsmem[192 + t]),
                         fmaxf(rowsmem[384 + t], rowsmem[576 + t]));
        int p = ti * TILEM + t;
        atomicMax(&g_keys[((size_t)(rl * BATCH + b) * PADP + p) * BATCH + c], enc_f(mr));
        float mc = fmaxf(fmaxf(colsmem[t], colsmem[192 + t]), colsmem[384 + t]);
        int q = tj * TILEM + t;
        atomicMax(&g_keys[((size_t)(rl * BATCH + c) * PADP + q) * BATCH + b], enc_f(mc));
    }
}

// ---------------- score / image / bilinear ----------------
__global__ void score_kernel() {
    int idx = blockIdx.x * 256 + threadIdx.x;
    if (idx >= BATCH * PATCHES) return;
    int b = idx / PATCHES;
    int p = idx % PATCHES;

    float sum = 0.f;
    #pragma unroll
    for (int rl = 0; rl < NRL; ++rl) {
        const unsigned* k = &g_keys[((size_t)(rl * BATCH + b) * PADP + p) * BATCH];
        float d1 = 1e30f, d2 = 1e30f;
        #pragma unroll
        for (int cc = 0; cc < BATCH; ++cc) {
            if (cc == b) continue;
            float dot = dec_f(k[cc]);
            float d = sqrtf(fmaxf(2.0f - 2.0f * dot, 0.0f));
            if (d < d1) { d2 = d1; d1 = d; }
            else if (d < d2) { d2 = d; }
        }
        sum += 0.5f * (d1 + d2);
    }
    g_scores[idx] = sum * (1.0f / 12.0f);
}

__global__ void image_kernel(float* __restrict__ out) {
    int b = blockIdx.x;
    int t = threadIdx.x;
    float m = -1e30f;
    for (int p = t; p < PATCHES; p += 256) m = fmaxf(m, g_scores[b * PATCHES + p]);
    #pragma unroll
    for (int o = 16; o > 0; o >>= 1) m = fmaxf(m, __shfl_xor_sync(0xffffffffu, m, o));
    __shared__ float ws[8];
    if ((t & 31) == 0) ws[t >> 5] = m;
    __syncthreads();
    if (t == 0) {
        float mm = ws[0];
        #pragma unroll
        for (int w = 1; w < 8; ++w) mm = fmaxf(mm, ws[w]);
        out[b] = mm;
    }
}

__global__ void bilinear_kernel(float* __restrict__ out) {
    int idx = blockIdx.x * 256 + threadIdx.x;
    if (idx >= BATCH * OUTH * OUTW) return;
    int b = idx / (OUTH * OUTW);
    int rr = idx % (OUTH * OUTW);
    int y = rr / OUTW, x = rr % OUTW;

    const float sc = 23.0f / 335.0f;
    float fy = (float)y * sc;
    float fx = (float)x * sc;
    int y0 = (int)floorf(fy); int y1 = min(y0 + 1, PHN - 1);
    int x0 = (int)floorf(fx); int x1 = min(x0 + 1, PWN - 1);
    float wy = fy - (float)y0;
    float wx = fx - (float)x0;

    const float* s = g_scores + b * PATCHES;
    float f00 = s[y0 * PWN + x0];
    float f01 = s[y0 * PWN + x1];
    float f10 = s[y1 * PWN + x0];
    float f11 = s[y1 * PWN + x1];

    out[BATCH + idx] = f00 * (1.f - wy) * (1.f - wx) + f01 * (1.f - wy) * wx
                     + f10 * wy * (1.f - wx)         + f11 * wy * wx;
}

// ---------------- launch ----------------
extern "C" void kernel_launch(void* const* d_in, const int* in_sizes, int n_in,
                              void* d_out, int out_size) {
    const float* feat = (const float*)d_in[0];
    float* out = (float*)d_out;

    cudaFuncSetAttribute(gemm_max_mma, cudaFuncAttributeMaxDynamicSharedMemorySize, SMEM_DYN);

    init_keys_kernel<<<(NRL * BATCH * PADP * BATCH + 255) / 256, 256>>>();
    pool_norm_kernel<<<dim3(PATCHES, BATCH, L_LAYERS), 256>>>(feat);
    gemm_max_mma<<<dim3(9, NPAIRS, NRL), NTHR, SMEM_DYN>>>();
    score_kernel<<<(BATCH * PATCHES + 255) / 256, 256>>>();
    image_kernel<<<BATCH, 256>>>(out);
    bilinear_kernel<<<(BATCH * OUTH * OUTW + 255) / 256, 256>>>(out);
}

// round 8
// speedup vs baseline: 1.2217x; 1.2217x over previous
#include <cuda_runtime.h>
#include <cuda_fp16.h>
#include <cstdint>
#include <math.h>

#define L_LAYERS 4
#define BATCH    8
#define PHN      24
#define PWN      24
#define PATCHES  576
#define DIM      1024
#define NRL      12
#define NPAIRS   28
#define OUTH     336
#define OUTW     336
#define PADP     640            // storage stride (rows 576+ unused)
#define TILEM    192
#define KS       32             // k per slab
#define NSLAB    32             // 1024/32
#define STAGES   3
#define ROWB     80             // smem row stride bytes (64 data + 16 pad)
#define STAGEB   (2 * TILEM * ROWB)  // A+B per stage = 30720
#define SMEM_DYN (STAGES * STAGEB)   // 92160 -> 2 CTAs/SM
#define NTHR     256            // 8 warps, warp tile 96x48 (2x4)

// ---------------- device scratch ----------------
__device__ __align__(16) __half g_featn[(size_t)NRL * BATCH * PADP * DIM];
__device__ unsigned g_keys[NRL * BATCH * PADP * BATCH];
__device__ float    g_scores[BATCH * PATCHES];

__device__ __forceinline__ unsigned enc_f(float x) {
    unsigned u = __float_as_uint(x);
    return (u & 0x80000000u) ? ~u : (u | 0x80000000u);
}
__device__ __forceinline__ float dec_f(unsigned k) {
    unsigned u = (k & 0x80000000u) ? (k & 0x7FFFFFFFu) : ~k;
    return __uint_as_float(u);
}

__device__ __forceinline__ uint32_t smem_u32(const void* p) {
    uint32_t a;
    asm("{ .reg .u64 t; cvta.to.shared.u64 t, %1; cvt.u32.u64 %0, t; }" : "=r"(a) : "l"(p));
    return a;
}

#define CP16(dst, src) asm volatile("cp.async.cg.shared.global [%0], [%1], 16;" :: "r"(dst), "l"(src) : "memory")
#define CP_COMMIT()    asm volatile("cp.async.commit_group;" ::: "memory")

#define LDSM_X4(r0, r1, r2, r3, a) \
    asm volatile("ldmatrix.sync.aligned.m8n8.x4.shared.b16 {%0,%1,%2,%3}, [%4];" \
        : "=r"(r0), "=r"(r1), "=r"(r2), "=r"(r3) : "r"(a))

// fp16 in, fp16 accumulate: D/C are 2 x b32 (4 packed halves)
#define MMA16816H(c, a, b) \
    asm volatile("mma.sync.aligned.m16n8k16.row.col.f16.f16.f16.f16 " \
        "{%0,%1}, {%2,%3,%4,%5}, {%6,%7}, {%0,%1};" \
        : "+r"((c)[0]), "+r"((c)[1]) \
        : "r"((a)[0]), "r"((a)[1]), "r"((a)[2]), "r"((a)[3]), "r"((b)[0]), "r"((b)[1]))

// ---------------- init ----------------
__global__ void init_keys_kernel() {
    int i = blockIdx.x * 256 + threadIdx.x;
    if (i < NRL * BATCH * PADP * BATCH) g_keys[i] = 0u;
}

// ---------------- pool (all 3 radii, one 5x5 read) + normalize -> fp16 ------
__global__ void pool_norm_kernel(const float* __restrict__ feat) {
    int p = blockIdx.x, b = blockIdx.y, l = blockIdx.z;
    int ph = p / PWN, pw = p % PWN;
    int t = threadIdx.x;
    int d0 = t * 4;

    const float* base = feat + ((size_t)(l * BATCH + b) * PATCHES) * DIM;

    float4 s5 = make_float4(0.f, 0.f, 0.f, 0.f);
    float4 s3 = make_float4(0.f, 0.f, 0.f, 0.f);
    float4 s1 = make_float4(0.f, 0.f, 0.f, 0.f);

    #pragma unroll
    for (int dy = -2; dy <= 2; ++dy) {
        int y = ph + dy;
        if ((unsigned)y >= (unsigned)PHN) continue;
        #pragma unroll
        for (int dx = -2; dx <= 2; ++dx) {
            int x = pw + dx;
            if ((unsigned)x >= (unsigned)PWN) continue;
            const float4 v = *(const float4*)(base + (size_t)(y * PWN + x) * DIM + d0);
            s5.x += v.x; s5.y += v.y; s5.z += v.z; s5.w += v.w;
            if (dy >= -1 && dy <= 1 && dx >= -1 && dx <= 1) {
                s3.x += v.x; s3.y += v.y; s3.z += v.z; s3.w += v.w;
                if (dy == 0 && dx == 0) s1 = v;
            }
        }
    }
    s3.x *= (1.f/9.f);  s3.y *= (1.f/9.f);  s3.z *= (1.f/9.f);  s3.w *= (1.f/9.f);
    s5.x *= (1.f/25.f); s5.y *= (1.f/25.f); s5.z *= (1.f/25.f); s5.w *= (1.f/25.f);

    float q1 = s1.x*s1.x + s1.y*s1.y + s1.z*s1.z + s1.w*s1.w;
    float q3 = s3.x*s3.x + s3.y*s3.y + s3.z*s3.z + s3.w*s3.w;
    float q5 = s5.x*s5.x + s5.y*s5.y + s5.z*s5.z + s5.w*s5.w;
    #pragma unroll
    for (int o = 16; o > 0; o >>= 1) {
        q1 += __shfl_xor_sync(0xffffffffu, q1, o);
        q3 += __shfl_xor_sync(0xffffffffu, q3, o);
        q5 += __shfl_xor_sync(0xffffffffu, q5, o);
    }
    __shared__ float ws[3][8];
    __shared__ float rn[3];
    if ((t & 31) == 0) { ws[0][t >> 5] = q1; ws[1][t >> 5] = q3; ws[2][t >> 5] = q5; }
    __syncthreads();
    if (t < 3) {
        float x = 0.f;
        #pragma unroll
        for (int w = 0; w < 8; ++w) x += ws[t][w];
        rn[t] = rsqrtf(x);
    }
    __syncthreads();

    float4 vv[3] = { s1, s3, s5 };
    #pragma unroll
    for (int ri = 0; ri < 3; ++ri) {
        float r = rn[ri];
        __half2 lo = __floats2half2_rn(vv[ri].x * r, vv[ri].y * r);
        __half2 hi = __floats2half2_rn(vv[ri].z * r, vv[ri].w * r);
        uint2 pk = make_uint2(*(unsigned*)&lo, *(unsigned*)&hi);
        int z = ri * 4 + l;
        *(uint2*)(g_featn + ((size_t)(z * BATCH + b) * PADP + p) * DIM + d0) = pk;
    }
}

// ---------------- fp16 mma.sync fused GEMM + bidirectional max ----------------
// CTA tile 192x192, 8 warps (2x4) of 96x48, K slabs of 32, 3-stage, 2 CTAs/SM.
__device__ __forceinline__ void load_slab(uint32_t sA, const char* gA, const char* gB, int t) {
    int r0 = t >> 2, c = t & 3;          // r0: 0..63
    #pragma unroll
    for (int h = 0; h < 3; ++h) {
        int r = r0 + h * 64;
        CP16(sA + r * ROWB + c * 16, gA + (size_t)r * (DIM * 2) + c * 16);
    }
    #pragma unroll
    for (int h = 0; h < 3; ++h) {
        int r = r0 + h * 64;
        CP16(sA + (TILEM + r) * ROWB + c * 16, gB + (size_t)r * (DIM * 2) + c * 16);
    }
}

__global__ void __launch_bounds__(NTHR, 2) gemm_max_mma() {
    extern __shared__ __align__(16) char dsm[];
    uint32_t sbase = smem_u32(dsm);

    int t = threadIdx.x;
    int wid = t >> 5, lane = t & 31;
    int warp_m = wid & 1;               // 2 row groups of 96
    int warp_n = wid >> 1;              // 4 col groups of 48

    int tile = blockIdx.x;
    int ti = tile / 3, tj = tile % 3;
    int pair = blockIdx.y, rl = blockIdx.z;

    int b = 0, rem = pair;
    #pragma unroll
    for (int bb = 0; bb < 7; ++bb) {
        int cnt = 7 - bb;
        if (rem < cnt) { b = bb; break; }
        rem -= cnt;
    }
    int c = b + 1 + rem;

    const char* gA = (const char*)(g_featn + ((size_t)(rl * BATCH + b) * PADP + ti * TILEM) * DIM);
    const char* gB = (const char*)(g_featn + ((size_t)(rl * BATCH + c) * PADP + tj * TILEM) * DIM);

    uint32_t acc[6][6][2];
    #pragma unroll
    for (int mi = 0; mi < 6; ++mi)
        #pragma unroll
        for (int ni = 0; ni < 6; ++ni) { acc[mi][ni][0] = 0u; acc[mi][ni][1] = 0u; }

    uint32_t aoff = (uint32_t)((warp_m * 96 + (lane & 15)) * ROWB + (lane >> 4) * 16);
    uint32_t boff = (uint32_t)((TILEM + warp_n * 48 + (lane >> 4) * 8 + (lane & 7)) * ROWB + ((lane >> 3) & 1) * 16);

    // prologue: slabs 0,1 into stages 0,1
    #pragma unroll
    for (int s = 0; s < 2; ++s) {
        load_slab(sbase + s * STAGEB, gA + (size_t)s * (KS * 2), gB + (size_t)s * (KS * 2), t);
        CP_COMMIT();
    }

    for (int kc = 0; kc < NSLAB; ++kc) {
        if (kc < NSLAB - 1) asm volatile("cp.async.wait_group 1;" ::: "memory");
        else                asm volatile("cp.async.wait_group 0;" ::: "memory");
        __syncthreads();

        // prefetch slab kc+2 into stage (kc+2)%3 (read last at iter kc-1; safe past barrier)
        if (kc + 2 < NSLAB) {
            int bufw = (kc + 2) % 3;
            load_slab(sbase + bufw * STAGEB,
                      gA + (size_t)(kc + 2) * (KS * 2), gB + (size_t)(kc + 2) * (KS * 2), t);
            CP_COMMIT();
        }

        uint32_t Sb = sbase + (kc % 3) * STAGEB;

        #pragma unroll
        for (int ks = 0; ks < 2; ++ks) {
            uint32_t afr[6][4];
            #pragma unroll
            for (int mi = 0; mi < 6; ++mi)
                LDSM_X4(afr[mi][0], afr[mi][1], afr[mi][2], afr[mi][3],
                        Sb + aoff + mi * 16 * ROWB + ks * 32);
            uint32_t bfr[6][2];
            #pragma unroll
            for (int np = 0; np < 3; ++np)
                LDSM_X4(bfr[np * 2][0], bfr[np * 2][1], bfr[np * 2 + 1][0], bfr[np * 2 + 1][1],
                        Sb + boff + np * 16 * ROWB + ks * 32);
            #pragma unroll
            for (int mi = 0; mi < 6; ++mi)
                #pragma unroll
                for (int ni = 0; ni < 6; ++ni)
                    MMA16816H(acc[mi][ni], afr[mi], bfr[ni]);
        }
    }

    // ---------------- epilogue: bidirectional max ----------------
    // last loop read stage 31%3 = 1; stage-0 smem region is free.
    float* rowsmem = (float*)dsm;            // [4][192] by warp_n
    float* colsmem = rowsmem + 4 * 192;      // [2][192] by warp_m

    // row maxes: reg0 = row r (lane>>2), reg1 = row r+8; halves are col pair
    #pragma unroll
    for (int mi = 0; mi < 6; ++mi) {
        __half2 h0 = __float2half2_rn(-60000.f), h1 = h0;
        #pragma unroll
        for (int ni = 0; ni < 6; ++ni) {
            h0 = __hmax2(h0, *(__half2*)&acc[mi][ni][0]);
            h1 = __hmax2(h1, *(__half2*)&acc[mi][ni][1]);
        }
        float rm0 = fmaxf(__low2float(h0), __high2float(h0));
        float rm1 = fmaxf(__low2float(h1), __high2float(h1));
        #pragma unroll
        for (int o = 1; o < 4; o <<= 1) {
            rm0 = fmaxf(rm0, __shfl_xor_sync(0xffffffffu, rm0, o));
            rm1 = fmaxf(rm1, __shfl_xor_sync(0xffffffffu, rm1, o));
        }
        if ((lane & 3) == 0) {
            int lr = warp_m * 96 + mi * 16 + (lane >> 2);
            rowsmem[warp_n * 192 + lr]     = rm0;
            rowsmem[warp_n * 192 + lr + 8] = rm1;
        }
    }

    // col maxes: half .x = col 2j, .y = col 2j+1 (j = lane&3)
    #pragma unroll
    for (int ni = 0; ni < 6; ++ni) {
        __half2 hm = __float2half2_rn(-60000.f);
        #pragma unroll
        for (int mi = 0; mi < 6; ++mi) {
            hm = __hmax2(hm, *(__half2*)&acc[mi][ni][0]);
            hm = __hmax2(hm, *(__half2*)&acc[mi][ni][1]);
        }
        float cm0 = __low2float(hm);
        float cm1 = __high2float(hm);
        #pragma unroll
        for (int o = 4; o < 32; o <<= 1) {
            cm0 = fmaxf(cm0, __shfl_xor_sync(0xffffffffu, cm0, o));
            cm1 = fmaxf(cm1, __shfl_xor_sync(0xffffffffu, cm1, o));
        }
        if (lane < 4) {
            int lc = warp_n * 48 + ni * 8 + lane * 2;
            colsmem[warp_m * 192 + lc]     = cm0;
            colsmem[warp_m * 192 + lc + 1] = cm1;
        }
    }
    __syncthreads();

    if (t < 192) {
        float mr = fmaxf(fmaxf(rowsmem[t], rowsmem[192 + t]),
                         fmaxf(rowsmem[384 + t], rowsmem[576 + t]));
        int p = ti * TILEM + t;
        atomicMax(&g_keys[((size_t)(rl * BATCH + b) * PADP + p) * BATCH + c], enc_f(mr));
        float mc = fmaxf(colsmem[t], colsmem[192 + t]);
        int q = tj * TILEM + t;
        atomicMax(&g_keys[((size_t)(rl * BATCH + c) * PADP + q) * BATCH + b], enc_f(mc));
    }
}

// ---------------- score / image / bilinear ----------------
__global__ void score_kernel() {
    int idx = blockIdx.x * 256 + threadIdx.x;
    if (idx >= BATCH * PATCHES) return;
    int b = idx / PATCHES;
    int p = idx % PATCHES;

    float sum = 0.f;
    #pragma unroll
    for (int rl = 0; rl < NRL; ++rl) {
        const unsigned* k = &g_keys[((size_t)(rl * BATCH + b) * PADP + p) * BATCH];
        float d1 = 1e30f, d2 = 1e30f;
        #pragma unroll
        for (int cc = 0; cc < BATCH; ++cc) {
            if (cc == b) continue;
            float dot = dec_f(k[cc]);
            float d = sqrtf(fmaxf(2.0f - 2.0f * dot, 0.0f));
            if (d < d1) { d2 = d1; d1 = d; }
            else if (d < d2) { d2 = d; }
        }
        sum += 0.5f * (d1 + d2);
    }
    g_scores[idx] = sum * (1.0f / 12.0f);
}

__global__ void image_kernel(float* __restrict__ out) {
    int b = blockIdx.x;
    int t = threadIdx.x;
    float m = -1e30f;
    for (int p = t; p < PATCHES; p += 256) m = fmaxf(m, g_scores[b * PATCHES + p]);
    #pragma unroll
    for (int o = 16; o > 0; o >>= 1) m = fmaxf(m, __shfl_xor_sync(0xffffffffu, m, o));
    __shared__ float ws[8];
    if ((t & 31) == 0) ws[t >> 5] = m;
    __syncthreads();
    if (t == 0) {
        float mm = ws[0];
        #pragma unroll
        for (int w = 1; w < 8; ++w) mm = fmaxf(mm, ws[w]);
        out[b] = mm;
    }
}

__global__ void bilinear_kernel(float* __restrict__ out) {
    int idx = blockIdx.x * 256 + threadIdx.x;
    if (idx >= BATCH * OUTH * OUTW) return;
    int b = idx / (OUTH * OUTW);
    int rr = idx % (OUTH * OUTW);
    int y = rr / OUTW, x = rr % OUTW;

    const float sc = 23.0f / 335.0f;
    float fy = (float)y * sc;
    float fx = (float)x * sc;
    int y0 = (int)floorf(fy); int y1 = min(y0 + 1, PHN - 1);
    int x0 = (int)floorf(fx); int x1 = min(x0 + 1, PWN - 1);
    float wy = fy - (float)y0;
    float wx = fx - (float)x0;

    const float* s = g_scores + b * PATCHES;
    float f00 = s[y0 * PWN + x0];
    float f01 = s[y0 * PWN + x1];
    float f10 = s[y1 * PWN + x0];
    float f11 = s[y1 * PWN + x1];

    out[BATCH + idx] = f00 * (1.f - wy) * (1.f - wx) + f01 * (1.f - wy) * wx
                     + f10 * wy * (1.f - wx)         + f11 * wy * wx;
}

// ---------------- launch ----------------
extern "C" void kernel_launch(void* const* d_in, const int* in_sizes, int n_in,
                              void* d_out, int out_size) {
    const float* feat = (const float*)d_in[0];
    float* out = (float*)d_out;

    cudaFuncSetAttribute(gemm_max_mma, cudaFuncAttributeMaxDynamicSharedMemorySize, SMEM_DYN);

    init_keys_kernel<<<(NRL * BATCH * PADP * BATCH + 255) / 256, 256>>>();
    pool_norm_kernel<<<dim3(PATCHES, BATCH, L_LAYERS), 256>>>(feat);
    gemm_max_mma<<<dim3(9, NPAIRS, NRL), NTHR, SMEM_DYN>>>();
    score_kernel<<<(BATCH * PATCHES + 255) / 256, 256>>>();
    image_kernel<<<BATCH, 256>>>(out);
    bilinear_kernel<<<(BATCH * OUTH * OUTW + 255) / 256, 256>>>(out);
}

// round 9
// speedup vs baseline: 1.2892x; 1.0553x over previous
#include <cuda_runtime.h>
#include <cuda_fp16.h>
#include <cstdint>
#include <math.h>

#define L_LAYERS 4
#define BATCH    8
#define PHN      24
#define PWN      24
#define PATCHES  576
#define DIM      1024
#define NRL      12
#define NPAIRS   28
#define OUTH     336
#define OUTW     336
#define PADP     640            // storage stride (rows 576+ unused)
#define TILEM    192
#define KS       32             // k per slab
#define NSLAB    32             // 1024/32
#define STAGES   3
#define ROWB     80             // smem row stride bytes (64 data + 16 pad)
#define STAGEB   (2 * TILEM * ROWB)  // A+B per stage = 30720
#define SMEM_DYN (STAGES * STAGEB)   // 92160 -> 2 CTAs/SM
#define NTHR     128            // 4 warps, warp tile 96x96 (2x2)

// ---------------- device scratch ----------------
__device__ __align__(16) __half g_featn[(size_t)NRL * BATCH * PADP * DIM];
__device__ unsigned g_keys[NRL * BATCH * PADP * BATCH];
__device__ float    g_scores[BATCH * PATCHES];

__device__ __forceinline__ unsigned enc_f(float x) {
    unsigned u = __float_as_uint(x);
    return (u & 0x80000000u) ? ~u : (u | 0x80000000u);
}
__device__ __forceinline__ float dec_f(unsigned k) {
    unsigned u = (k & 0x80000000u) ? (k & 0x7FFFFFFFu) : ~k;
    return __uint_as_float(u);
}

__device__ __forceinline__ uint32_t smem_u32(const void* p) {
    uint32_t a;
    asm("{ .reg .u64 t; cvta.to.shared.u64 t, %1; cvt.u32.u64 %0, t; }" : "=r"(a) : "l"(p));
    return a;
}

#define CP16(dst, src) asm volatile("cp.async.cg.shared.global [%0], [%1], 16;" :: "r"(dst), "l"(src) : "memory")
#define CP_COMMIT()    asm volatile("cp.async.commit_group;" ::: "memory")

#define LDSM_X4(r0, r1, r2, r3, a) \
    asm volatile("ldmatrix.sync.aligned.m8n8.x4.shared.b16 {%0,%1,%2,%3}, [%4];" \
        : "=r"(r0), "=r"(r1), "=r"(r2), "=r"(r3) : "r"(a))

// fp16 in, fp16 accumulate
#define MMA16816H(c, a, b) \
    asm volatile("mma.sync.aligned.m16n8k16.row.col.f16.f16.f16.f16 " \
        "{%0,%1}, {%2,%3,%4,%5}, {%6,%7}, {%0,%1};" \
        : "+r"((c)[0]), "+r"((c)[1]) \
        : "r"((a)[0]), "r"((a)[1]), "r"((a)[2]), "r"((a)[3]), "r"((b)[0]), "r"((b)[1]))

// ---------------- init ----------------
__global__ void init_keys_kernel() {
    int i = blockIdx.x * 256 + threadIdx.x;
    if (i < NRL * BATCH * PADP * BATCH) g_keys[i] = 0u;
}

// ---------------- pool (all 3 radii, one 5x5 read) + normalize -> fp16 ------
__global__ void pool_norm_kernel(const float* __restrict__ feat) {
    int p = blockIdx.x, b = blockIdx.y, l = blockIdx.z;
    int ph = p / PWN, pw = p % PWN;
    int t = threadIdx.x;
    int d0 = t * 4;

    const float* base = feat + ((size_t)(l * BATCH + b) * PATCHES) * DIM;

    float4 s5 = make_float4(0.f, 0.f, 0.f, 0.f);
    float4 s3 = make_float4(0.f, 0.f, 0.f, 0.f);
    float4 s1 = make_float4(0.f, 0.f, 0.f, 0.f);

    #pragma unroll
    for (int dy = -2; dy <= 2; ++dy) {
        int y = ph + dy;
        if ((unsigned)y >= (unsigned)PHN) continue;
        #pragma unroll
        for (int dx = -2; dx <= 2; ++dx) {
            int x = pw + dx;
            if ((unsigned)x >= (unsigned)PWN) continue;
            const float4 v = *(const float4*)(base + (size_t)(y * PWN + x) * DIM + d0);
            s5.x += v.x; s5.y += v.y; s5.z += v.z; s5.w += v.w;
            if (dy >= -1 && dy <= 1 && dx >= -1 && dx <= 1) {
                s3.x += v.x; s3.y += v.y; s3.z += v.z; s3.w += v.w;
                if (dy == 0 && dx == 0) s1 = v;
            }
        }
    }
    s3.x *= (1.f/9.f);  s3.y *= (1.f/9.f);  s3.z *= (1.f/9.f);  s3.w *= (1.f/9.f);
    s5.x *= (1.f/25.f); s5.y *= (1.f/25.f); s5.z *= (1.f/25.f); s5.w *= (1.f/25.f);

    float q1 = s1.x*s1.x + s1.y*s1.y + s1.z*s1.z + s1.w*s1.w;
    float q3 = s3.x*s3.x + s3.y*s3.y + s3.z*s3.z + s3.w*s3.w;
    float q5 = s5.x*s5.x + s5.y*s5.y + s5.z*s5.z + s5.w*s5.w;
    #pragma unroll
    for (int o = 16; o > 0; o >>= 1) {
        q1 += __shfl_xor_sync(0xffffffffu, q1, o);
        q3 += __shfl_xor_sync(0xffffffffu, q3, o);
        q5 += __shfl_xor_sync(0xffffffffu, q5, o);
    }
    __shared__ float ws[3][8];
    __shared__ float rn[3];
    if ((t & 31) == 0) { ws[0][t >> 5] = q1; ws[1][t >> 5] = q3; ws[2][t >> 5] = q5; }
    __syncthreads();
    if (t < 3) {
        float x = 0.f;
        #pragma unroll
        for (int w = 0; w < 8; ++w) x += ws[t][w];
        rn[t] = rsqrtf(x);
    }
    __syncthreads();

    float4 vv[3] = { s1, s3, s5 };
    #pragma unroll
    for (int ri = 0; ri < 3; ++ri) {
        float r = rn[ri];
        __half2 lo = __floats2half2_rn(vv[ri].x * r, vv[ri].y * r);
        __half2 hi = __floats2half2_rn(vv[ri].z * r, vv[ri].w * r);
        uint2 pk = make_uint2(*(unsigned*)&lo, *(unsigned*)&hi);
        int z = ri * 4 + l;
        *(uint2*)(g_featn + ((size_t)(z * BATCH + b) * PADP + p) * DIM + d0) = pk;
    }
}

// ---------------- fp16 mma.sync fused GEMM + bidirectional max ----------------
// CTA tile 192x192, 4 warps (2x2) of 96x96, K slabs of 32, 3-stage, 2 CTAs/SM.
__device__ __forceinline__ void load_slab(uint32_t sA, const char* gA, const char* gB, int t) {
    int r0 = t >> 2, c = t & 3;          // r0: 0..31
    #pragma unroll
    for (int h = 0; h < 6; ++h) {
        int r = r0 + h * 32;
        CP16(sA + r * ROWB + c * 16, gA + (size_t)r * (DIM * 2) + c * 16);
    }
    #pragma unroll
    for (int h = 0; h < 6; ++h) {
        int r = r0 + h * 32;
        CP16(sA + (TILEM + r) * ROWB + c * 16, gB + (size_t)r * (DIM * 2) + c * 16);
    }
}

__global__ void __launch_bounds__(NTHR, 2) gemm_max_mma() {
    extern __shared__ __align__(16) char dsm[];
    uint32_t sbase = smem_u32(dsm);

    int t = threadIdx.x;
    int wid = t >> 5, lane = t & 31;
    int warp_m = wid & 1;               // 2 row groups of 96
    int warp_n = wid >> 1;              // 2 col groups of 96

    int tile = blockIdx.x;
    int ti = tile / 3, tj = tile % 3;
    int pair = blockIdx.y, rl = blockIdx.z;

    int b = 0, rem = pair;
    #pragma unroll
    for (int bb = 0; bb < 7; ++bb) {
        int cnt = 7 - bb;
        if (rem < cnt) { b = bb; break; }
        rem -= cnt;
    }
    int c = b + 1 + rem;

    const char* gA = (const char*)(g_featn + ((size_t)(rl * BATCH + b) * PADP + ti * TILEM) * DIM);
    const char* gB = (const char*)(g_featn + ((size_t)(rl * BATCH + c) * PADP + tj * TILEM) * DIM);

    uint32_t acc[6][12][2];
    #pragma unroll
    for (int mi = 0; mi < 6; ++mi)
        #pragma unroll
        for (int ni = 0; ni < 12; ++ni) { acc[mi][ni][0] = 0u; acc[mi][ni][1] = 0u; }

    uint32_t aoff = (uint32_t)((warp_m * 96 + (lane & 15)) * ROWB + (lane >> 4) * 16);
    uint32_t boff = (uint32_t)((TILEM + warp_n * 96 + (lane >> 4) * 8 + (lane & 7)) * ROWB + ((lane >> 3) & 1) * 16);

    // prologue: slabs 0,1 into stages 0,1
    #pragma unroll
    for (int s = 0; s < 2; ++s) {
        load_slab(sbase + s * STAGEB, gA + (size_t)s * (KS * 2), gB + (size_t)s * (KS * 2), t);
        CP_COMMIT();
    }

    for (int kc = 0; kc < NSLAB; ++kc) {
        if (kc < NSLAB - 1) asm volatile("cp.async.wait_group 1;" ::: "memory");
        else                asm volatile("cp.async.wait_group 0;" ::: "memory");
        __syncthreads();

        if (kc + 2 < NSLAB) {
            int bufw = (kc + 2) % 3;
            load_slab(sbase + bufw * STAGEB,
                      gA + (size_t)(kc + 2) * (KS * 2), gB + (size_t)(kc + 2) * (KS * 2), t);
            CP_COMMIT();
        }

        uint32_t Sb = sbase + (kc % 3) * STAGEB;

        #pragma unroll
        for (int ks = 0; ks < 2; ++ks) {
            uint32_t afr[6][4];
            #pragma unroll
            for (int mi = 0; mi < 6; ++mi)
                LDSM_X4(afr[mi][0], afr[mi][1], afr[mi][2], afr[mi][3],
                        Sb + aoff + mi * 16 * ROWB + ks * 32);
            uint32_t bfr[12][2];
            #pragma unroll
            for (int np = 0; np < 6; ++np)
                LDSM_X4(bfr[np * 2][0], bfr[np * 2][1], bfr[np * 2 + 1][0], bfr[np * 2 + 1][1],
                        Sb + boff + np * 16 * ROWB + ks * 32);
            #pragma unroll
            for (int mi = 0; mi < 6; ++mi)
                #pragma unroll
                for (int ni = 0; ni < 12; ++ni)
                    MMA16816H(acc[mi][ni], afr[mi], bfr[ni]);
        }
    }

    // ---------------- epilogue: bidirectional max ----------------
    // last loop read stage 31%3 = 1; stage-0 smem region is free.
    float* rowsmem = (float*)dsm;            // [2][192] by warp_n
    float* colsmem = rowsmem + 2 * 192;      // [2][192] by warp_m

    #pragma unroll
    for (int mi = 0; mi < 6; ++mi) {
        __half2 h0 = __float2half2_rn(-60000.f), h1 = h0;
        #pragma unroll
        for (int ni = 0; ni < 12; ++ni) {
            h0 = __hmax2(h0, *(__half2*)&acc[mi][ni][0]);
            h1 = __hmax2(h1, *(__half2*)&acc[mi][ni][1]);
        }
        float rm0 = fmaxf(__low2float(h0), __high2float(h0));
        float rm1 = fmaxf(__low2float(h1), __high2float(h1));
        #pragma unroll
        for (int o = 1; o < 4; o <<= 1) {
            rm0 = fmaxf(rm0, __shfl_xor_sync(0xffffffffu, rm0, o));
            rm1 = fmaxf(rm1, __shfl_xor_sync(0xffffffffu, rm1, o));
        }
        if ((lane & 3) == 0) {
            int lr = warp_m * 96 + mi * 16 + (lane >> 2);
            rowsmem[warp_n * 192 + lr]     = rm0;
            rowsmem[warp_n * 192 + lr + 8] = rm1;
        }
    }

    #pragma unroll
    for (int ni = 0; ni < 12; ++ni) {
        __half2 hm = __float2half2_rn(-60000.f);
        #pragma unroll
        for (int mi = 0; mi < 6; ++mi) {
            hm = __hmax2(hm, *(__half2*)&acc[mi][ni][0]);
            hm = __hmax2(hm, *(__half2*)&acc[mi][ni][1]);
        }
        float cm0 = __low2float(hm);
        float cm1 = __high2float(hm);
        #pragma unroll
        for (int o = 4; o < 32; o <<= 1) {
            cm0 = fmaxf(cm0, __shfl_xor_sync(0xffffffffu, cm0, o));
            cm1 = fmaxf(cm1, __shfl_xor_sync(0xffffffffu, cm1, o));
        }
        if (lane < 4) {
            int lc = warp_n * 96 + ni * 8 + lane * 2;
            colsmem[warp_m * 192 + lc]     = cm0;
            colsmem[warp_m * 192 + lc + 1] = cm1;
        }
    }
    __syncthreads();

    for (int idx = t; idx < 192; idx += NTHR) {
        float mr = fmaxf(rowsmem[idx], rowsmem[192 + idx]);
        int p = ti * TILEM + idx;
        atomicMax(&g_keys[((size_t)(rl * BATCH + b) * PADP + p) * BATCH + c], enc_f(mr));
        float mc = fmaxf(colsmem[idx], colsmem[192 + idx]);
        int q = tj * TILEM + idx;
        atomicMax(&g_keys[((size_t)(rl * BATCH + c) * PADP + q) * BATCH + b], enc_f(mc));
    }
}

// ---------------- score / image / bilinear ----------------
__global__ void score_kernel() {
    int idx = blockIdx.x * 128 + threadIdx.x;
    if (idx >= BATCH * PATCHES) return;
    int b = idx / PATCHES;
    int p = idx % PATCHES;

    float sum = 0.f;
    #pragma unroll
    for (int rl = 0; rl < NRL; ++rl) {
        const unsigned* k = &g_keys[((size_t)(rl * BATCH + b) * PADP + p) * BATCH];
        float d1 = 1e30f, d2 = 1e30f;
        #pragma unroll
        for (int cc = 0; cc < BATCH; ++cc) {
            if (cc == b) continue;
            float dot = dec_f(k[cc]);
            float d = sqrtf(fmaxf(2.0f - 2.0f * dot, 0.0f));
            if (d < d1) { d2 = d1; d1 = d; }
            else if (d < d2) { d2 = d; }
        }
        sum += 0.5f * (d1 + d2);
    }
    g_scores[idx] = sum * (1.0f / 12.0f);
}

__global__ void image_kernel(float* __restrict__ out) {
    int b = blockIdx.x;
    int t = threadIdx.x;
    float m = -1e30f;
    for (int p = t; p < PATCHES; p += 256) m = fmaxf(m, g_scores[b * PATCHES + p]);
    #pragma unroll
    for (int o = 16; o > 0; o >>= 1) m = fmaxf(m, __shfl_xor_sync(0xffffffffu, m, o));
    __shared__ float ws[8];
    if ((t & 31) == 0) ws[t >> 5] = m;
    __syncthreads();
    if (t == 0) {
        float mm = ws[0];
        #pragma unroll
        for (int w = 1; w < 8; ++w) mm = fmaxf(mm, ws[w]);
        out[b] = mm;
    }
}

__global__ void bilinear_kernel(float* __restrict__ out) {
    int idx = blockIdx.x * 256 + threadIdx.x;
    if (idx >= BATCH * OUTH * OUTW) return;
    int b = idx / (OUTH * OUTW);
    int rr = idx % (OUTH * OUTW);
    int y = rr / OUTW, x = rr % OUTW;

    const float sc = 23.0f / 335.0f;
    float fy = (float)y * sc;
    float fx = (float)x * sc;
    int y0 = (int)floorf(fy); int y1 = min(y0 + 1, PHN - 1);
    int x0 = (int)floorf(fx); int x1 = min(x0 + 1, PWN - 1);
    float wy = fy - (float)y0;
    float wx = fx - (float)x0;

    const float* s = g_scores + b * PATCHES;
    float f00 = s[y0 * PWN + x0];
    float f01 = s[y0 * PWN + x1];
    float f10 = s[y1 * PWN + x0];
    float f11 = s[y1 * PWN + x1];

    out[BATCH + idx] = f00 * (1.f - wy) * (1.f - wx) + f01 * (1.f - wy) * wx
                     + f10 * wy * (1.f - wx)         + f11 * wy * wx;
}

// ---------------- launch ----------------
extern "C" void kernel_launch(void* const* d_in, const int* in_sizes, int n_in,
                              void* d_out, int out_size) {
    const float* feat = (const float*)d_in[0];
    float* out = (float*)d_out;

    cudaFuncSetAttribute(gemm_max_mma, cudaFuncAttributeMaxDynamicSharedMemorySize, SMEM_DYN);

    init_keys_kernel<<<(NRL * BATCH * PADP * BATCH + 255) / 256, 256>>>();
    pool_norm_kernel<<<dim3(PATCHES, BATCH, L_LAYERS), 256>>>(feat);
    gemm_max_mma<<<dim3(9, NPAIRS, NRL), NTHR, SMEM_DYN>>>();
    score_kernel<<<(BATCH * PATCHES + 127) / 128, 128>>>();
    image_kernel<<<BATCH, 256>>>(out);
    bilinear_kernel<<<(BATCH * OUTH * OUTW + 255) / 256, 256>>>(out);
}

// round 10
// speedup vs baseline: 1.5288x; 1.1858x over previous
#include <cuda_runtime.h>
#include <cuda.h>
#include <cuda_fp16.h>
#include <cstdint>
#include <math.h>

#define L_LAYERS 4
#define BATCH    8
#define PHN      24
#define PWN      24
#define PATCHES  576
#define DIM      1024
#define NRL      12
#define NPAIRS   28
#define OUTH     336
#define OUTW     336
#define PADP     640
#define TILEM    192
#define KS       32             // k per slab (64 bytes fp16)
#define NSLAB    32
#define NTHR     128            // 4 warps, warp tile 96x96
#define MATB     (TILEM * 64)   // one matrix slab in smem = 12288
#define STAGEB   (2 * MATB)     // 24576
#define TXB      STAGEB
#define SMEM_DYN (2048 + 4 * STAGEB)   // align slack + barriers + 4 stages

// ---------------- device scratch ----------------
__device__ __align__(128) __half g_featn[(size_t)NRL * BATCH * PADP * DIM];
__device__ unsigned g_keys[NRL * BATCH * PADP * BATCH];
__device__ float    g_scores[BATCH * PATCHES];

__device__ __forceinline__ unsigned enc_f(float x) {
    unsigned u = __float_as_uint(x);
    return (u & 0x80000000u) ? ~u : (u | 0x80000000u);
}
__device__ __forceinline__ float dec_f(unsigned k) {
    unsigned u = (k & 0x80000000u) ? (k & 0x7FFFFFFFu) : ~k;
    return __uint_as_float(u);
}
__device__ __forceinline__ uint32_t smem_u32(const void* p) {
    uint32_t a;
    asm("{ .reg .u64 t; cvta.to.shared.u64 t, %1; cvt.u32.u64 %0, t; }" : "=r"(a) : "l"(p));
    return a;
}

#define MBAR_INIT(a, n) asm volatile("mbarrier.init.shared.b64 [%0], %1;" :: "r"(a), "r"(n) : "memory")
#define MBAR_EXPECT(a, tx) asm volatile("mbarrier.arrive.expect_tx.shared.b64 _, [%0], %1;" :: "r"(a), "r"(tx) : "memory")
#define MBAR_WAIT(a, ph) do { \
    uint32_t _m = (a), _p = (ph), _d; \
    asm volatile("{ .reg .pred p; mbarrier.try_wait.parity.acquire.cta.shared::cta.b64 p, [%1], %2; selp.b32 %0,1,0,p; }" \
        : "=r"(_d) : "r"(_m), "r"(_p) : "memory"); \
    if (!_d) { asm volatile("{ .reg .pred P1; WL_%=: mbarrier.try_wait.parity.acquire.cta.shared::cta.b64 P1, [%0], %1, 0x989680; @P1 bra.uni WD_%=; bra.uni WL_%=; WD_%=: }" \
        :: "r"(_m), "r"(_p) : "memory"); } \
} while (0)

#define TMA_LOAD_2D(dst, map, cx, cy, mbar) \
    asm volatile("cp.async.bulk.tensor.2d.shared::cta.global.tile.mbarrier::complete_tx::bytes " \
        "[%0], [%1, {%2, %3}], [%4];" \
        :: "r"(dst), "l"(map), "r"(cx), "r"(cy), "r"(mbar) : "memory")

#define LDSM_X4(r0, r1, r2, r3, a) \
    asm volatile("ldmatrix.sync.aligned.m8n8.x4.shared.b16 {%0,%1,%2,%3}, [%4];" \
        : "=r"(r0), "=r"(r1), "=r"(r2), "=r"(r3) : "r"(a))

#define MMA16816H(c, a, b) \
    asm volatile("mma.sync.aligned.m16n8k16.row.col.f16.f16.f16.f16 " \
        "{%0,%1}, {%2,%3,%4,%5}, {%6,%7}, {%0,%1};" \
        : "+r"((c)[0]), "+r"((c)[1]) \
        : "r"((a)[0]), "r"((a)[1]), "r"((a)[2]), "r"((a)[3]), "r"((b)[0]), "r"((b)[1]))

// ---------------- init ----------------
__global__ void init_keys_kernel() {
    int i = blockIdx.x * 256 + threadIdx.x;
    if (i < NRL * BATCH * PADP * BATCH) g_keys[i] = 0u;
}

// ---------------- pool (all 3 radii, one 5x5 read) + normalize -> fp16 ------
__global__ void pool_norm_kernel(const float* __restrict__ feat) {
    int p = blockIdx.x, b = blockIdx.y, l = blockIdx.z;
    int ph = p / PWN, pw = p % PWN;
    int t = threadIdx.x;
    int d0 = t * 4;

    const float* base = feat + ((size_t)(l * BATCH + b) * PATCHES) * DIM;

    float4 s5 = make_float4(0.f, 0.f, 0.f, 0.f);
    float4 s3 = make_float4(0.f, 0.f, 0.f, 0.f);
    float4 s1 = make_float4(0.f, 0.f, 0.f, 0.f);

    #pragma unroll
    for (int dy = -2; dy <= 2; ++dy) {
        int y = ph + dy;
        if ((unsigned)y >= (unsigned)PHN) continue;
        #pragma unroll
        for (int dx = -2; dx <= 2; ++dx) {
            int x = pw + dx;
            if ((unsigned)x >= (unsigned)PWN) continue;
            const float4 v = *(const float4*)(base + (size_t)(y * PWN + x) * DIM + d0);
            s5.x += v.x; s5.y += v.y; s5.z += v.z; s5.w += v.w;
            if (dy >= -1 && dy <= 1 && dx >= -1 && dx <= 1) {
                s3.x += v.x; s3.y += v.y; s3.z += v.z; s3.w += v.w;
                if (dy == 0 && dx == 0) s1 = v;
            }
        }
    }
    s3.x *= (1.f/9.f);  s3.y *= (1.f/9.f);  s3.z *= (1.f/9.f);  s3.w *= (1.f/9.f);
    s5.x *= (1.f/25.f); s5.y *= (1.f/25.f); s5.z *= (1.f/25.f); s5.w *= (1.f/25.f);

    float q1 = s1.x*s1.x + s1.y*s1.y + s1.z*s1.z + s1.w*s1.w;
    float q3 = s3.x*s3.x + s3.y*s3.y + s3.z*s3.z + s3.w*s3.w;
    float q5 = s5.x*s5.x + s5.y*s5.y + s5.z*s5.z + s5.w*s5.w;
    #pragma unroll
    for (int o = 16; o > 0; o >>= 1) {
        q1 += __shfl_xor_sync(0xffffffffu, q1, o);
        q3 += __shfl_xor_sync(0xffffffffu, q3, o);
        q5 += __shfl_xor_sync(0xffffffffu, q5, o);
    }
    __shared__ float ws[3][8];
    __shared__ float rn[3];
    if ((t & 31) == 0) { ws[0][t >> 5] = q1; ws[1][t >> 5] = q3; ws[2][t >> 5] = q5; }
    __syncthreads();
    if (t < 3) {
        float x = 0.f;
        #pragma unroll
        for (int w = 0; w < 8; ++w) x += ws[t][w];
        rn[t] = rsqrtf(x);
    }
    __syncthreads();

    float4 vv[3] = { s1, s3, s5 };
    #pragma unroll
    for (int ri = 0; ri < 3; ++ri) {
        float r = rn[ri];
        __half2 lo = __floats2half2_rn(vv[ri].x * r, vv[ri].y * r);
        __half2 hi = __floats2half2_rn(vv[ri].z * r, vv[ri].w * r);
        uint2 pk = make_uint2(*(unsigned*)&lo, *(unsigned*)&hi);
        int z = ri * 4 + l;
        *(uint2*)(g_featn + ((size_t)(z * BATCH + b) * PADP + p) * DIM + d0) = pk;
    }
}

// ---------------- TMA + fp16 mma fused GEMM + bidirectional max --------------
// CTA tile 192x192, 4 warps (2x2) of 96x96, K slabs of 32 halves (64B), 4 TMA stages.
__global__ void __launch_bounds__(NTHR, 2) gemm_max_mma(const __grid_constant__ CUtensorMap tmap) {
    extern __shared__ __align__(16) char dsm[];
    uint32_t sraw = smem_u32(dsm);
    uint32_t ub   = (sraw + 1023) & ~1023u;     // barriers at ub, stages at ub+1024
    uint32_t sstg = ub + 1024;

    int t = threadIdx.x;
    int wid = t >> 5, lane = t & 31;
    int warp_m = wid & 1;
    int warp_n = wid >> 1;

    int tile = blockIdx.x;
    int ti = tile / 3, tj = tile % 3;
    int pair = blockIdx.y, rl = blockIdx.z;

    int b = 0, rem = pair;
    #pragma unroll
    for (int bb = 0; bb < 7; ++bb) {
        int cnt = 7 - bb;
        if (rem < cnt) { b = bb; break; }
        rem -= cnt;
    }
    int c = b + 1 + rem;

    int rowA = (rl * BATCH + b) * PADP + ti * TILEM;
    int rowB = (rl * BATCH + c) * PADP + tj * TILEM;

    // init barriers + prologue TMA (3 slabs)
    if (t == 0) {
        #pragma unroll
        for (int s = 0; s < 4; ++s) MBAR_INIT(ub + s * 8, 1);
        asm volatile("fence.proxy.async.shared::cta;" ::: "memory");
    }
    __syncthreads();
    if (t == 0) {
        #pragma unroll
        for (int s = 0; s < 3; ++s) {
            MBAR_EXPECT(ub + s * 8, TXB);
            TMA_LOAD_2D(sstg + s * STAGEB,        &tmap, s * 64, rowA, ub + s * 8);
            TMA_LOAD_2D(sstg + s * STAGEB + MATB, &tmap, s * 64, rowB, ub + s * 8);
        }
    }

    uint32_t acc[6][12][2];
    #pragma unroll
    for (int mi = 0; mi < 6; ++mi)
        #pragma unroll
        for (int ni = 0; ni < 12; ++ni) { acc[mi][ni][0] = 0u; acc[mi][ni][1] = 0u; }

    // SW64-swizzled LDSM address precompute (c bits[5:4] ^= row bits[2:1])
    int rA = warp_m * 96 + (lane & 15);
    int xorA = (rA & 6) << 3;
    uint32_t koA0 = (uint32_t)(((lane >> 4) * 16) ^ xorA);
    uint32_t koA1 = (uint32_t)((((lane >> 4) * 16) + 32) ^ xorA);
    uint32_t abase = (uint32_t)(rA * 64);

    int rB = warp_n * 96 + (lane >> 4) * 8 + (lane & 7);
    int xorB = (rB & 6) << 3;
    uint32_t koB0 = (uint32_t)((((lane >> 3) & 1) * 16) ^ xorB);
    uint32_t koB1 = (uint32_t)(((((lane >> 3) & 1) * 16) + 32) ^ xorB);
    uint32_t bbase = (uint32_t)(MATB + rB * 64);

    for (int kc = 0; kc < NSLAB; ++kc) {
        int st = kc & 3;
        MBAR_WAIT(ub + st * 8, (kc >> 2) & 1);
        __syncthreads();   // all warps done reading stage (kc-1)&3 == (kc+3)&3

        if (t == 0 && kc + 3 < NSLAB) {
            int sn = (kc + 3) & 3;
            MBAR_EXPECT(ub + sn * 8, TXB);
            TMA_LOAD_2D(sstg + sn * STAGEB,        &tmap, (kc + 3) * 64, rowA, ub + sn * 8);
            TMA_LOAD_2D(sstg + sn * STAGEB + MATB, &tmap, (kc + 3) * 64, rowB, ub + sn * 8);
        }

        uint32_t Sb = sstg + st * STAGEB;

        #pragma unroll
        for (int ks = 0; ks < 2; ++ks) {
            uint32_t koa = ks ? koA1 : koA0;
            uint32_t kob = ks ? koB1 : koB0;
            uint32_t afr[6][4];
            #pragma unroll
            for (int mi = 0; mi < 6; ++mi)
                LDSM_X4(afr[mi][0], afr[mi][1], afr[mi][2], afr[mi][3],
                        Sb + abase + mi * 1024 + koa);
            uint32_t bfr[12][2];
            #pragma unroll
            for (int np = 0; np < 6; ++np)
                LDSM_X4(bfr[np * 2][0], bfr[np * 2][1], bfr[np * 2 + 1][0], bfr[np * 2 + 1][1],
                        Sb + bbase + np * 1024 + kob);
            #pragma unroll
            for (int mi = 0; mi < 6; ++mi)
                #pragma unroll
                for (int ni = 0; ni < 12; ++ni)
                    MMA16816H(acc[mi][ni], afr[mi], bfr[ni]);
        }
    }

    // ---------------- epilogue: bidirectional max ----------------
    // last loop read stage 3; stage-0 region (sstg) free.
    float* rowsmem = (float*)(dsm + (sstg - sraw));          // [2][192] by warp_n
    float* colsmem = rowsmem + 2 * 192;                      // [2][192] by warp_m

    #pragma unroll
    for (int mi = 0; mi < 6; ++mi) {
        __half2 h0 = __float2half2_rn(-60000.f), h1 = h0;
        #pragma unroll
        for (int ni = 0; ni < 12; ++ni) {
            h0 = __hmax2(h0, *(__half2*)&acc[mi][ni][0]);
            h1 = __hmax2(h1, *(__half2*)&acc[mi][ni][1]);
        }
        float rm0 = fmaxf(__low2float(h0), __high2float(h0));
        float rm1 = fmaxf(__low2float(h1), __high2float(h1));
        #pragma unroll
        for (int o = 1; o < 4; o <<= 1) {
            rm0 = fmaxf(rm0, __shfl_xor_sync(0xffffffffu, rm0, o));
            rm1 = fmaxf(rm1, __shfl_xor_sync(0xffffffffu, rm1, o));
        }
        if ((lane & 3) == 0) {
            int lr = warp_m * 96 + mi * 16 + (lane >> 2);
            rowsmem[warp_n * 192 + lr]     = rm0;
            rowsmem[warp_n * 192 + lr + 8] = rm1;
        }
    }

    #pragma unroll
    for (int ni = 0; ni < 12; ++ni) {
        __half2 hm = __float2half2_rn(-60000.f);
        #pragma unroll
        for (int mi = 0; mi < 6; ++mi) {
            hm = __hmax2(hm, *(__half2*)&acc[mi][ni][0]);
            hm = __hmax2(hm, *(__half2*)&acc[mi][ni][1]);
        }
        float cm0 = __low2float(hm);
        float cm1 = __high2float(hm);
        #pragma unroll
        for (int o = 4; o < 32; o <<= 1) {
            cm0 = fmaxf(cm0, __shfl_xor_sync(0xffffffffu, cm0, o));
            cm1 = fmaxf(cm1, __shfl_xor_sync(0xffffffffu, cm1, o));
        }
        if (lane < 4) {
            int lc = warp_n * 96 + ni * 8 + lane * 2;
            colsmem[warp_m * 192 + lc]     = cm0;
            colsmem[warp_m * 192 + lc + 1] = cm1;
        }
    }
    __syncthreads();

    for (int idx = t; idx < 192; idx += NTHR) {
        float mr = fmaxf(rowsmem[idx], rowsmem[192 + idx]);
        int p = ti * TILEM + idx;
        atomicMax(&g_keys[((size_t)(rl * BATCH + b) * PADP + p) * BATCH + c], enc_f(mr));
        float mc = fmaxf(colsmem[idx], colsmem[192 + idx]);
        int q = tj * TILEM + idx;
        atomicMax(&g_keys[((size_t)(rl * BATCH + c) * PADP + q) * BATCH + b], enc_f(mc));
    }
}

// ---------------- score / image / bilinear ----------------
__global__ void score_kernel() {
    int idx = blockIdx.x * 128 + threadIdx.x;
    if (idx >= BATCH * PATCHES) return;
    int b = idx / PATCHES;
    int p = idx % PATCHES;

    float sum = 0.f;
    #pragma unroll
    for (int rl = 0; rl < NRL; ++rl) {
        const unsigned* k = &g_keys[((size_t)(rl * BATCH + b) * PADP + p) * BATCH];
        float d1 = 1e30f, d2 = 1e30f;
        #pragma unroll
        for (int cc = 0; cc < BATCH; ++cc) {
            if (cc == b) continue;
            float dot = dec_f(k[cc]);
            float d = sqrtf(fmaxf(2.0f - 2.0f * dot, 0.0f));
            if (d < d1) { d2 = d1; d1 = d; }
            else if (d < d2) { d2 = d; }
        }
        sum += 0.5f * (d1 + d2);
    }
    g_scores[idx] = sum * (1.0f / 12.0f);
}

__global__ void image_kernel(float* __restrict__ out) {
    int b = blockIdx.x;
    int t = threadIdx.x;
    float m = -1e30f;
    for (int p = t; p < PATCHES; p += 256) m = fmaxf(m, g_scores[b * PATCHES + p]);
    #pragma unroll
    for (int o = 16; o > 0; o >>= 1) m = fmaxf(m, __shfl_xor_sync(0xffffffffu, m, o));
    __shared__ float ws[8];
    if ((t & 31) == 0) ws[t >> 5] = m;
    __syncthreads();
    if (t == 0) {
        float mm = ws[0];
        #pragma unroll
        for (int w = 1; w < 8; ++w) mm = fmaxf(mm, ws[w]);
        out[b] = mm;
    }
}

__global__ void bilinear_kernel(float* __restrict__ out) {
    int idx = blockIdx.x * 256 + threadIdx.x;
    if (idx >= BATCH * OUTH * OUTW) return;
    int b = idx / (OUTH * OUTW);
    int rr = idx % (OUTH * OUTW);
    int y = rr / OUTW, x = rr % OUTW;

    const float sc = 23.0f / 335.0f;
    float fy = (float)y * sc;
    float fx = (float)x * sc;
    int y0 = (int)floorf(fy); int y1 = min(y0 + 1, PHN - 1);
    int x0 = (int)floorf(fx); int x1 = min(x0 + 1, PWN - 1);
    float wy = fy - (float)y0;
    float wx = fx - (float)x0;

    const float* s = g_scores + b * PATCHES;
    float f00 = s[y0 * PWN + x0];
    float f01 = s[y0 * PWN + x1];
    float f10 = s[y1 * PWN + x0];
    float f11 = s[y1 * PWN + x1];

    out[BATCH + idx] = f00 * (1.f - wy) * (1.f - wx) + f01 * (1.f - wy) * wx
                     + f10 * wy * (1.f - wx)         + f11 * wy * wx;
}

// ---------------- launch ----------------
typedef CUresult (*PFN_TMapEncode)(
    CUtensorMap*, CUtensorMapDataType, cuuint32_t, void*,
    const cuuint64_t*, const cuuint64_t*, const cuuint32_t*, const cuuint32_t*,
    CUtensorMapInterleave, CUtensorMapSwizzle, CUtensorMapL2promotion,
    CUtensorMapFloatOOBfill);

extern "C" void kernel_launch(void* const* d_in, const int* in_sizes, int n_in,
                              void* d_out, int out_size) {
    const float* feat = (const float*)d_in[0];
    float* out = (float*)d_out;

    // Build TMA descriptor: uint8 2D tensor (2048 bytes x 61440 rows), box 64x192, SW64.
    static CUtensorMap tmap;   // static: host memory persists for graph replay
    {
        void* fn = nullptr;
        cudaDriverEntryPointQueryResult qres;
        cudaGetDriverEntryPointByVersion("cuTensorMapEncodeTiled", &fn, 12000,
                                         cudaEnableDefault, &qres);
        void* gptr = nullptr;
        cudaGetSymbolAddress(&gptr, g_featn);
        cuuint64_t dims[2]    = { (cuuint64_t)(DIM * 2), (cuuint64_t)(NRL * BATCH * PADP) };
        cuuint64_t strides[1] = { (cuuint64_t)(DIM * 2) };
        cuuint32_t box[2]     = { 64u, (cuuint32_t)TILEM };
        cuuint32_t estr[2]    = { 1u, 1u };
        if (fn) {
            ((PFN_TMapEncode)fn)(&tmap, CU_TENSOR_MAP_DATA_TYPE_UINT8, 2, gptr,
                                 dims, strides, box, estr,
                                 CU_TENSOR_MAP_INTERLEAVE_NONE,
                                 CU_TENSOR_MAP_SWIZZLE_64B,
                                 CU_TENSOR_MAP_L2_PROMOTION_L2_128B,
                                 CU_TENSOR_MAP_FLOAT_OOB_FILL_NONE);
        }
    }

    cudaFuncSetAttribute(gemm_max_mma, cudaFuncAttributeMaxDynamicSharedMemorySize, SMEM_DYN);

    init_keys_kernel<<<(NRL * BATCH * PADP * BATCH + 255) / 256, 256>>>();
    pool_norm_kernel<<<dim3(PATCHES, BATCH, L_LAYERS), 256>>>(feat);
    gemm_max_mma<<<dim3(9, NPAIRS, NRL), NTHR, SMEM_DYN>>>(tmap);
    score_kernel<<<(BATCH * PATCHES + 127) / 128, 128>>>();
    image_kernel<<<BATCH, 256>>>(out);
    bilinear_kernel<<<(BATCH * OUTH * OUTW + 255) / 256, 256>>>(out);
}

// round 11
// speedup vs baseline: 1.5790x; 1.0329x over previous
#include <cuda_runtime.h>
#include <cuda.h>
#include <cuda_fp16.h>
#include <cstdint>
#include <math.h>

#define L_LAYERS 4
#define BATCH    8
#define PHN      24
#define PWN      24
#define PATCHES  576
#define DIM      1024
#define NRL      12
#define NPAIRS   28
#define OUTH     336
#define OUTW     336
#define PADP     640
#define TILEM    192
#define KS       64             // k per slab (128 bytes fp16) - SW128
#define NSLAB    16
#define NTHR     128            // 4 warps, warp tile 96x96
#define MATB     (TILEM * 128)  // one matrix slab in smem = 24576
#define STAGEB   (2 * MATB)     // 49152
#define TXB      STAGEB
#define SMEM_DYN (2048 + 2 * STAGEB)   // 100352 -> 2 CTAs/SM

// ---------------- device scratch ----------------
__device__ __align__(128) __half g_featn[(size_t)NRL * BATCH * PADP * DIM];
__device__ unsigned g_keys[NRL * BATCH * PADP * BATCH];
__device__ float    g_scores[BATCH * PATCHES];

__device__ __forceinline__ unsigned enc_f(float x) {
    unsigned u = __float_as_uint(x);
    return (u & 0x80000000u) ? ~u : (u | 0x80000000u);
}
__device__ __forceinline__ float dec_f(unsigned k) {
    unsigned u = (k & 0x80000000u) ? (k & 0x7FFFFFFFu) : ~k;
    return __uint_as_float(u);
}
__device__ __forceinline__ uint32_t smem_u32(const void* p) {
    uint32_t a;
    asm("{ .reg .u64 t; cvta.to.shared.u64 t, %1; cvt.u32.u64 %0, t; }" : "=r"(a) : "l"(p));
    return a;
}

#define MBAR_INIT(a, n) asm volatile("mbarrier.init.shared.b64 [%0], %1;" :: "r"(a), "r"(n) : "memory")
#define MBAR_EXPECT(a, tx) asm volatile("mbarrier.arrive.expect_tx.shared.b64 _, [%0], %1;" :: "r"(a), "r"(tx) : "memory")
#define MBAR_WAIT(a, ph) do { \
    uint32_t _m = (a), _p = (ph), _d; \
    asm volatile("{ .reg .pred p; mbarrier.try_wait.parity.acquire.cta.shared::cta.b64 p, [%1], %2; selp.b32 %0,1,0,p; }" \
        : "=r"(_d) : "r"(_m), "r"(_p) : "memory"); \
    if (!_d) { asm volatile("{ .reg .pred P1; WL_%=: mbarrier.try_wait.parity.acquire.cta.shared::cta.b64 P1, [%0], %1, 0x989680; @P1 bra.uni WD_%=; bra.uni WL_%=; WD_%=: }" \
        :: "r"(_m), "r"(_p) : "memory"); } \
} while (0)

#define TMA_LOAD_2D(dst, map, cx, cy, mbar) \
    asm volatile("cp.async.bulk.tensor.2d.shared::cta.global.tile.mbarrier::complete_tx::bytes " \
        "[%0], [%1, {%2, %3}], [%4];" \
        :: "r"(dst), "l"(map), "r"(cx), "r"(cy), "r"(mbar) : "memory")

#define LDSM_X4(r0, r1, r2, r3, a) \
    asm volatile("ldmatrix.sync.aligned.m8n8.x4.shared.b16 {%0,%1,%2,%3}, [%4];" \
        : "=r"(r0), "=r"(r1), "=r"(r2), "=r"(r3) : "r"(a))

#define MMA16816H(c, a, b) \
    asm volatile("mma.sync.aligned.m16n8k16.row.col.f16.f16.f16.f16 " \
        "{%0,%1}, {%2,%3,%4,%5}, {%6,%7}, {%0,%1};" \
        : "+r"((c)[0]), "+r"((c)[1]) \
        : "r"((a)[0]), "r"((a)[1]), "r"((a)[2]), "r"((a)[3]), "r"((b)[0]), "r"((b)[1]))

// ---------------- init ----------------
__global__ void init_keys_kernel() {
    int i = blockIdx.x * 256 + threadIdx.x;
    if (i < NRL * BATCH * PADP * BATCH) g_keys[i] = 0u;
}

// ---------------- pool (all 3 radii, one 5x5 read) + normalize -> fp16 ------
__global__ void pool_norm_kernel(const float* __restrict__ feat) {
    int p = blockIdx.x, b = blockIdx.y, l = blockIdx.z;
    int ph = p / PWN, pw = p % PWN;
    int t = threadIdx.x;
    int d0 = t * 4;

    const float* base = feat + ((size_t)(l * BATCH + b) * PATCHES) * DIM;

    float4 s5 = make_float4(0.f, 0.f, 0.f, 0.f);
    float4 s3 = make_float4(0.f, 0.f, 0.f, 0.f);
    float4 s1 = make_float4(0.f, 0.f, 0.f, 0.f);

    #pragma unroll
    for (int dy = -2; dy <= 2; ++dy) {
        int y = ph + dy;
        if ((unsigned)y >= (unsigned)PHN) continue;
        #pragma unroll
        for (int dx = -2; dx <= 2; ++dx) {
            int x = pw + dx;
            if ((unsigned)x >= (unsigned)PWN) continue;
            const float4 v = *(const float4*)(base + (size_t)(y * PWN + x) * DIM + d0);
            s5.x += v.x; s5.y += v.y; s5.z += v.z; s5.w += v.w;
            if (dy >= -1 && dy <= 1 && dx >= -1 && dx <= 1) {
                s3.x += v.x; s3.y += v.y; s3.z += v.z; s3.w += v.w;
                if (dy == 0 && dx == 0) s1 = v;
            }
        }
    }
    s3.x *= (1.f/9.f);  s3.y *= (1.f/9.f);  s3.z *= (1.f/9.f);  s3.w *= (1.f/9.f);
    s5.x *= (1.f/25.f); s5.y *= (1.f/25.f); s5.z *= (1.f/25.f); s5.w *= (1.f/25.f);

    float q1 = s1.x*s1.x + s1.y*s1.y + s1.z*s1.z + s1.w*s1.w;
    float q3 = s3.x*s3.x + s3.y*s3.y + s3.z*s3.z + s3.w*s3.w;
    float q5 = s5.x*s5.x + s5.y*s5.y + s5.z*s5.z + s5.w*s5.w;
    #pragma unroll
    for (int o = 16; o > 0; o >>= 1) {
        q1 += __shfl_xor_sync(0xffffffffu, q1, o);
        q3 += __shfl_xor_sync(0xffffffffu, q3, o);
        q5 += __shfl_xor_sync(0xffffffffu, q5, o);
    }
    __shared__ float ws[3][8];
    __shared__ float rn[3];
    if ((t & 31) == 0) { ws[0][t >> 5] = q1; ws[1][t >> 5] = q3; ws[2][t >> 5] = q5; }
    __syncthreads();
    if (t < 3) {
        float x = 0.f;
        #pragma unroll
        for (int w = 0; w < 8; ++w) x += ws[t][w];
        rn[t] = rsqrtf(x);
    }
    __syncthreads();

    float4 vv[3] = { s1, s3, s5 };
    #pragma unroll
    for (int ri = 0; ri < 3; ++ri) {
        float r = rn[ri];
        __half2 lo = __floats2half2_rn(vv[ri].x * r, vv[ri].y * r);
        __half2 hi = __floats2half2_rn(vv[ri].z * r, vv[ri].w * r);
        uint2 pk = make_uint2(*(unsigned*)&lo, *(unsigned*)&hi);
        int z = ri * 4 + l;
        *(uint2*)(g_featn + ((size_t)(z * BATCH + b) * PADP + p) * DIM + d0) = pk;
    }
}

// ---------------- TMA + fp16 mma fused GEMM + bidirectional max --------------
// CTA tile 192x192, 4 warps (2x2) of 96x96, K slabs of 64 halves (128B, SW128),
// 2-stage double buffer, 1 syncthreads per slab, 2 CTAs/SM.
__global__ void __launch_bounds__(NTHR, 2) gemm_max_mma(const __grid_constant__ CUtensorMap tmap) {
    extern __shared__ __align__(16) char dsm[];
    uint32_t sraw = smem_u32(dsm);
    uint32_t ub   = (sraw + 1023) & ~1023u;     // barriers at ub, stages at ub+1024
    uint32_t sstg = ub + 1024;

    int t = threadIdx.x;
    int wid = t >> 5, lane = t & 31;
    int warp_m = wid & 1;
    int warp_n = wid >> 1;

    int tile = blockIdx.x;
    int ti = tile / 3, tj = tile % 3;
    int pair = blockIdx.y, rl = blockIdx.z;

    int b = 0, rem = pair;
    #pragma unroll
    for (int bb = 0; bb < 7; ++bb) {
        int cnt = 7 - bb;
        if (rem < cnt) { b = bb; break; }
        rem -= cnt;
    }
    int c = b + 1 + rem;

    int rowA = (rl * BATCH + b) * PADP + ti * TILEM;
    int rowB = (rl * BATCH + c) * PADP + tj * TILEM;

    if (t == 0) {
        MBAR_INIT(ub, 1); MBAR_INIT(ub + 8, 1);
        asm volatile("fence.proxy.async.shared::cta;" ::: "memory");
    }
    __syncthreads();
    if (t == 0) {
        #pragma unroll
        for (int s = 0; s < 2; ++s) {
            MBAR_EXPECT(ub + s * 8, TXB);
            TMA_LOAD_2D(sstg + s * STAGEB,        &tmap, s * 128, rowA, ub + s * 8);
            TMA_LOAD_2D(sstg + s * STAGEB + MATB, &tmap, s * 128, rowB, ub + s * 8);
        }
    }

    uint32_t acc[6][12][2];
    #pragma unroll
    for (int mi = 0; mi < 6; ++mi)
        #pragma unroll
        for (int ni = 0; ni < 12; ++ni) { acc[mi][ni][0] = 0u; acc[mi][ni][1] = 0u; }

    // SW128 swizzle in a 128B-wide box: byte col c at row r lives at c ^ ((r&7)<<4)
    int rA = warp_m * 96 + (lane & 15);
    uint32_t xorA = (uint32_t)((rA & 7) << 4);
    uint32_t abase = (uint32_t)(rA * 128);
    uint32_t koA[4];
    #pragma unroll
    for (int ks = 0; ks < 4; ++ks)
        koA[ks] = (uint32_t)((ks * 32 + (lane >> 4) * 16)) ^ xorA;

    int rB = warp_n * 96 + (lane >> 4) * 8 + (lane & 7);
    uint32_t xorB = (uint32_t)((rB & 7) << 4);
    uint32_t bbase = (uint32_t)(MATB + rB * 128);
    uint32_t koB[4];
    #pragma unroll
    for (int ks = 0; ks < 4; ++ks)
        koB[ks] = (uint32_t)((ks * 32 + ((lane >> 3) & 1) * 16)) ^ xorB;

    for (int kc = 0; kc < NSLAB; ++kc) {
        int st = kc & 1;
        MBAR_WAIT(ub + st * 8, (kc >> 1) & 1);

        uint32_t Sb = sstg + st * STAGEB;

        #pragma unroll
        for (int ks = 0; ks < 4; ++ks) {
            uint32_t afr[6][4];
            #pragma unroll
            for (int mi = 0; mi < 6; ++mi)
                LDSM_X4(afr[mi][0], afr[mi][1], afr[mi][2], afr[mi][3],
                        Sb + abase + mi * 2048 + koA[ks]);
            uint32_t bfr[12][2];
            #pragma unroll
            for (int np = 0; np < 6; ++np)
                LDSM_X4(bfr[np * 2][0], bfr[np * 2][1], bfr[np * 2 + 1][0], bfr[np * 2 + 1][1],
                        Sb + bbase + np * 2048 + koB[ks]);
            #pragma unroll
            for (int mi = 0; mi < 6; ++mi)
                #pragma unroll
                for (int ni = 0; ni < 12; ++ni)
                    MMA16816H(acc[mi][ni], afr[mi], bfr[ni]);
        }

        __syncthreads();   // all warps finished reading stage st
        if (t == 0 && kc + 2 < NSLAB) {
            MBAR_EXPECT(ub + st * 8, TXB);
            TMA_LOAD_2D(Sb,        &tmap, (kc + 2) * 128, rowA, ub + st * 8);
            TMA_LOAD_2D(Sb + MATB, &tmap, (kc + 2) * 128, rowB, ub + st * 8);
        }
    }

    // ---------------- epilogue: bidirectional max ----------------
    // last slab (kc=15) read stage 1; stage-0 region (sstg) is free.
    float* rowsmem = (float*)(dsm + (sstg - sraw));          // [2][192] by warp_n
    float* colsmem = rowsmem + 2 * 192;                      // [2][192] by warp_m

    #pragma unroll
    for (int mi = 0; mi < 6; ++mi) {
        __half2 h0 = __float2half2_rn(-60000.f), h1 = h0;
        #pragma unroll
        for (int ni = 0; ni < 12; ++ni) {
            h0 = __hmax2(h0, *(__half2*)&acc[mi][ni][0]);
            h1 = __hmax2(h1, *(__half2*)&acc[mi][ni][1]);
        }
        float rm0 = fmaxf(__low2float(h0), __high2float(h0));
        float rm1 = fmaxf(__low2float(h1), __high2float(h1));
        #pragma unroll
        for (int o = 1; o < 4; o <<= 1) {
            rm0 = fmaxf(rm0, __shfl_xor_sync(0xffffffffu, rm0, o));
            rm1 = fmaxf(rm1, __shfl_xor_sync(0xffffffffu, rm1, o));
        }
        if ((lane & 3) == 0) {
            int lr = warp_m * 96 + mi * 16 + (lane >> 2);
            rowsmem[warp_n * 192 + lr]     = rm0;
            rowsmem[warp_n * 192 + lr + 8] = rm1;
        }
    }

    #pragma unroll
    for (int ni = 0; ni < 12; ++ni) {
        __half2 hm = __float2half2_rn(-60000.f);
        #pragma unroll
        for (int mi = 0; mi < 6; ++mi) {
            hm = __hmax2(hm, *(__half2*)&acc[mi][ni][0]);
            hm = __hmax2(hm, *(__half2*)&acc[mi][ni][1]);
        }
        float cm0 = __low2float(hm);
        float cm1 = __high2float(hm);
        #pragma unroll
        for (int o = 4; o < 32; o <<= 1) {
            cm0 = fmaxf(cm0, __shfl_xor_sync(0xffffffffu, cm0, o));
            cm1 = fmaxf(cm1, __shfl_xor_sync(0xffffffffu, cm1, o));
        }
        if (lane < 4) {
            int lc = warp_n * 96 + ni * 8 + lane * 2;
            colsmem[warp_m * 192 + lc]     = cm0;
            colsmem[warp_m * 192 + lc + 1] = cm1;
        }
    }
    __syncthreads();

    for (int idx = t; idx < 192; idx += NTHR) {
        float mr = fmaxf(rowsmem[idx], rowsmem[192 + idx]);
        int p = ti * TILEM + idx;
        atomicMax(&g_keys[((size_t)(rl * BATCH + b) * PADP + p) * BATCH + c], enc_f(mr));
        float mc = fmaxf(colsmem[idx], colsmem[192 + idx]);
        int q = tj * TILEM + idx;
        atomicMax(&g_keys[((size_t)(rl * BATCH + c) * PADP + q) * BATCH + b], enc_f(mc));
    }
}

// ---------------- score / image / bilinear ----------------
__global__ void score_kernel() {
    int idx = blockIdx.x * 128 + threadIdx.x;
    if (idx >= BATCH * PATCHES) return;
    int b = idx / PATCHES;
    int p = idx % PATCHES;

    float sum = 0.f;
    #pragma unroll
    for (int rl = 0; rl < NRL; ++rl) {
        const unsigned* k = &g_keys[((size_t)(rl * BATCH + b) * PADP + p) * BATCH];
        float d1 = 1e30f, d2 = 1e30f;
        #pragma unroll
        for (int cc = 0; cc < BATCH; ++cc) {
            if (cc == b) continue;
            float dot = dec_f(k[cc]);
            float d = sqrtf(fmaxf(2.0f - 2.0f * dot, 0.0f));
            if (d < d1) { d2 = d1; d1 = d; }
            else if (d < d2) { d2 = d; }
        }
        sum += 0.5f * (d1 + d2);
    }
    g_scores[idx] = sum * (1.0f / 12.0f);
}

__global__ void image_kernel(float* __restrict__ out) {
    int b = blockIdx.x;
    int t = threadIdx.x;
    float m = -1e30f;
    for (int p = t; p < PATCHES; p += 256) m = fmaxf(m, g_scores[b * PATCHES + p]);
    #pragma unroll
    for (int o = 16; o > 0; o >>= 1) m = fmaxf(m, __shfl_xor_sync(0xffffffffu, m, o));
    __shared__ float ws[8];
    if ((t & 31) == 0) ws[t >> 5] = m;
    __syncthreads();
    if (t == 0) {
        float mm = ws[0];
        #pragma unroll
        for (int w = 1; w < 8; ++w) mm = fmaxf(mm, ws[w]);
        out[b] = mm;
    }
}

__global__ void bilinear_kernel(float* __restrict__ out) {
    int idx = blockIdx.x * 256 + threadIdx.x;
    if (idx >= BATCH * OUTH * OUTW) return;
    int b = idx / (OUTH * OUTW);
    int rr = idx % (OUTH * OUTW);
    int y = rr / OUTW, x = rr % OUTW;

    const float sc = 23.0f / 335.0f;
    float fy = (float)y * sc;
    float fx = (float)x * sc;
    int y0 = (int)floorf(fy); int y1 = min(y0 + 1, PHN - 1);
    int x0 = (int)floorf(fx); int x1 = min(x0 + 1, PWN - 1);
    float wy = fy - (float)y0;
    float wx = fx - (float)x0;

    const float* s = g_scores + b * PATCHES;
    float f00 = s[y0 * PWN + x0];
    float f01 = s[y0 * PWN + x1];
    float f10 = s[y1 * PWN + x0];
    float f11 = s[y1 * PWN + x1];

    out[BATCH + idx] = f00 * (1.f - wy) * (1.f - wx) + f01 * (1.f - wy) * wx
                     + f10 * wy * (1.f - wx)         + f11 * wy * wx;
}

// ---------------- launch ----------------
typedef CUresult (*PFN_TMapEncode)(
    CUtensorMap*, CUtensorMapDataType, cuuint32_t, void*,
    const cuuint64_t*, const cuuint64_t*, const cuuint32_t*, const cuuint32_t*,
    CUtensorMapInterleave, CUtensorMapSwizzle, CUtensorMapL2promotion,
    CUtensorMapFloatOOBfill);

extern "C" void kernel_launch(void* const* d_in, const int* in_sizes, int n_in,
                              void* d_out, int out_size) {
    const float* feat = (const float*)d_in[0];
    float* out = (float*)d_out;

    // TMA descriptor: uint8 2D (2048 B x 61440 rows), box 128x192, SW128.
    static CUtensorMap tmap;
    {
        void* fn = nullptr;
        cudaDriverEntryPointQueryResult qres;
        cudaGetDriverEntryPointByVersion("cuTensorMapEncodeTiled", &fn, 12000,
                                         cudaEnableDefault, &qres);
        void* gptr = nullptr;
        cudaGetSymbolAddress(&gptr, g_featn);
        cuuint64_t dims[2]    = { (cuuint64_t)(DIM * 2), (cuuint64_t)(NRL * BATCH * PADP) };
        cuuint64_t strides[1] = { (cuuint64_t)(DIM * 2) };
        cuuint32_t box[2]     = { 128u, (cuuint32_t)TILEM };
        cuuint32_t estr[2]    = { 1u, 1u };
        if (fn) {
            ((PFN_TMapEncode)fn)(&tmap, CU_TENSOR_MAP_DATA_TYPE_UINT8, 2, gptr,
                                 dims, strides, box, estr,
                                 CU_TENSOR_MAP_INTERLEAVE_NONE,
                                 CU_TENSOR_MAP_SWIZZLE_128B,
                                 CU_TENSOR_MAP_L2_PROMOTION_L2_128B,
                                 CU_TENSOR_MAP_FLOAT_OOB_FILL_NONE);
        }
    }

    cudaFuncSetAttribute(gemm_max_mma, cudaFuncAttributeMaxDynamicSharedMemorySize, SMEM_DYN);

    init_keys_kernel<<<(NRL * BATCH * PADP * BATCH + 255) / 256, 256>>>();
    pool_norm_kernel<<<dim3(PATCHES, BATCH, L_LAYERS), 256>>>(feat);
    gemm_max_mma<<<dim3(9, NPAIRS, NRL), NTHR, SMEM_DYN>>>(tmap);
    score_kernel<<<(BATCH * PATCHES + 127) / 128, 128>>>();
    image_kernel<<<BATCH, 256>>>(out);
    bilinear_kernel<<<(BATCH * OUTH * OUTW + 255) / 256, 256>>>(out);
}